// round 15
// baseline (speedup 1.0000x reference)
#include <cuda_runtime.h>
#include <cfloat>

#define B_  2
#define T_  2048
#define C_  768
#define H_  12
#define HD_ 64
#define BH_ (B_*H_)

// ln(2048)/sqrt(64)
#define QSC 0.9530773732699245f

// scratch (static device globals; no allocs allowed)
__device__ float g_q[(size_t)BH_*HD_*T_];   // [bh][d][t], pre-scaled by QSC*qm[d]
__device__ float g_k[(size_t)BH_*HD_*T_];   // [bh][d][t]
__device__ float g_v[(size_t)BH_*T_*HD_];   // [bh][t][d]
__device__ float g_y[(size_t)B_*T_*C_];     // [b][t][h*HD]

// ---------------------------------------------------------------------------
// cp.async helpers
// ---------------------------------------------------------------------------
__device__ __forceinline__ void cpa16(void* dst, const void* src) {
    unsigned s = (unsigned)__cvta_generic_to_shared(dst);
    asm volatile("cp.async.cg.shared.global [%0], [%1], 16;\n" :: "r"(s), "l"(src));
}
__device__ __forceinline__ void cpa_commit() {
    asm volatile("cp.async.commit_group;\n");
}
template<int N> __device__ __forceinline__ void cpa_wait() {
    asm volatile("cp.async.wait_group %0;\n" :: "n"(N));
}

// ---------------------------------------------------------------------------
// packed f32x2 FMA helpers (SASS FFMA2 — halves issue pressure vs 2x FFMA)
// ---------------------------------------------------------------------------
typedef unsigned long long u64;

__device__ __forceinline__ void ffma2(u64& d, u64 a, u64 b) {
    asm("fma.rn.f32x2 %0, %1, %2, %0;" : "+l"(d) : "l"(a), "l"(b));
}
__device__ __forceinline__ u64 splat2(float x) {
    u64 r;
    asm("mov.b64 %0, {%1, %1};" : "=l"(r) : "f"(x));
    return r;
}
__device__ __forceinline__ float2 unpack2(u64 v) {
    float2 r;
    asm("mov.b64 {%0, %1}, %2;" : "=f"(r.x), "=f"(r.y) : "l"(v));
    return r;
}

// ---------------------------------------------------------------------------
// GEMM (round-14 committed config + forced 4 CTAs/SM): C[4096,768] = A @ W,
// 64x128 tiles, BK=16, cp.async double-buffered, 256 threads, 4x8 micro-tile,
// FFMA2, single-barrier pipeline loop.
// __launch_bounds__(256, 4) targets <=64 regs -> 4 resident CTAs/SM.
// mode: 0=q(transposed+scaled), 1=k(transposed), 2=v(row), 3=proj(out).
// ---------------------------------------------------------------------------
#define GBM 64
#define GBN 128
#define GBK 16

__global__ __launch_bounds__(256, 4)
void gemm64(const float* __restrict__ Asrc,
            const float* __restrict__ W0, const float* __restrict__ W1,
            const float* __restrict__ W2, const float* __restrict__ qm,
            float* __restrict__ outp, int proj)
{
    __shared__ float As[2][GBM][GBK];   // 8 KB
    __shared__ float Bs[2][GBK][GBN];   // 16 KB

    int mode = proj ? 3 : blockIdx.z;
    const float* W = (mode == 1) ? W1 : (mode == 2 ? W2 : W0);
    const float* A = proj ? (const float*)g_y : Asrc;

    int tid  = threadIdx.x;
    int row0 = blockIdx.y * GBM;
    int col0 = blockIdx.x * GBN;

    int ar = tid >> 2, ac = (tid & 3) * 4;     // A tile: 64 x 16
    int br = tid >> 4, bc = (tid & 15) * 8;    // B tile: 16 x 128
    int ty = tid >> 4, tx = tid & 15;

    // preload k-slice 0
    cpa16(&As[0][ar][ac],   &A[(size_t)(row0 + ar)*C_ + ac]);
    cpa16(&Bs[0][br][bc],   &W[(size_t)br*C_ + col0 + bc]);
    cpa16(&Bs[0][br][bc+4], &W[(size_t)br*C_ + col0 + bc + 4]);
    cpa_commit();

    u64 acc2[4][4];   // 4 rows x 4 col-pairs
#pragma unroll
    for (int i = 0; i < 4; i++)
#pragma unroll
        for (int j = 0; j < 4; j++) acc2[i][j] = 0ull;

    const int NIT = C_ / GBK;    // 48
    for (int it = 0; it < NIT; it++) {
        cpa_wait<0>();
        __syncthreads();
        if (it + 1 < NIT) {
            int nb = (it + 1) & 1;
            int k0 = (it + 1) * GBK;
            cpa16(&As[nb][ar][ac],   &A[(size_t)(row0 + ar)*C_ + k0 + ac]);
            cpa16(&Bs[nb][br][bc],   &W[(size_t)(k0 + br)*C_ + col0 + bc]);
            cpa16(&Bs[nb][br][bc+4], &W[(size_t)(k0 + br)*C_ + col0 + bc + 4]);
            cpa_commit();
        }

        int cb = it & 1;
#pragma unroll
        for (int kb = 0; kb < 4; kb++) {
            float a_[4][4];
            *(float4*)a_[0] = *(const float4*)&As[cb][ty*4+0][kb*4];
            *(float4*)a_[1] = *(const float4*)&As[cb][ty*4+1][kb*4];
            *(float4*)a_[2] = *(const float4*)&As[cb][ty*4+2][kb*4];
            *(float4*)a_[3] = *(const float4*)&As[cb][ty*4+3][kb*4];
#pragma unroll
            for (int kl = 0; kl < 4; kl++) {
                ulonglong2 b01 = *(const ulonglong2*)&Bs[cb][kb*4+kl][tx*4];
                ulonglong2 b23 = *(const ulonglong2*)&Bs[cb][kb*4+kl][64 + tx*4];
#pragma unroll
                for (int i = 0; i < 4; i++) {
                    u64 ap = splat2(a_[i][kl]);
                    ffma2(acc2[i][0], ap, b01.x);
                    ffma2(acc2[i][1], ap, b01.y);
                    ffma2(acc2[i][2], ap, b23.x);
                    ffma2(acc2[i][3], ap, b23.y);
                }
            }
        }
    }

    // unpack accumulators: acc[i][j] covers cols col0 + {tx*4..+3, 64+tx*4..+3}
    float acc[4][8];
#pragma unroll
    for (int i = 0; i < 4; i++) {
#pragma unroll
        for (int p = 0; p < 4; p++) {
            float2 v = unpack2(acc2[i][p]);
            acc[i][p*2]   = v.x;
            acc[i][p*2+1] = v.y;
        }
    }

    int m0 = row0 + ty*4;
    if (mode == 3) {
#pragma unroll
        for (int i = 0; i < 4; i++) {
            float* dst = &outp[(size_t)(m0 + i)*C_ + col0 + tx*4];
            *(float4*)dst      = make_float4(acc[i][0],acc[i][1],acc[i][2],acc[i][3]);
            *(float4*)(dst+64) = make_float4(acc[i][4],acc[i][5],acc[i][6],acc[i][7]);
        }
    } else {
        int b  = m0 >> 11, t0 = m0 & (T_-1);
        int h0 = col0 >> 6;
        if (mode == 2) {
#pragma unroll
            for (int i = 0; i < 4; i++) {
                float* d0p = &g_v[((size_t)(b*H_ + h0  )*T_ + (t0+i))*HD_ + tx*4];
                float* d1p = &g_v[((size_t)(b*H_ + h0+1)*T_ + (t0+i))*HD_ + tx*4];
                *(float4*)d0p = make_float4(acc[i][0],acc[i][1],acc[i][2],acc[i][3]);
                *(float4*)d1p = make_float4(acc[i][4],acc[i][5],acc[i][6],acc[i][7]);
            }
        } else {
            float* dstb = (mode == 0) ? g_q : g_k;
            size_t base0 = (size_t)(b*H_ + h0  )*HD_*T_;
            size_t base1 = (size_t)(b*H_ + h0+1)*HD_*T_;
#pragma unroll
            for (int e = 0; e < 4; e++) {
                int d = tx*4 + e;
                float sc = (mode == 0) ? QSC * __ldg(&qm[d]) : 1.f;
                *(float4*)&dstb[base0 + (size_t)d*T_ + t0] =
                    make_float4(acc[0][e]*sc, acc[1][e]*sc, acc[2][e]*sc, acc[3][e]*sc);
                *(float4*)&dstb[base1 + (size_t)d*T_ + t0] =
                    make_float4(acc[0][4+e]*sc, acc[1][4+e]*sc,
                                acc[2][4+e]*sc, acc[3][4+e]*sc);
            }
        }
    }
}

// ---------------------------------------------------------------------------
// GEMM-tiled sparse top-4 causal attention (round-14 committed, verbatim):
// MQ=64, NK=64, 256 threads, FFMA2, pair-balanced grid (16, 24), single-
// barrier tile loop. CTA x runs q-tile x then q-tile 31-x (uniform 33 tiles).
// ---------------------------------------------------------------------------
#define MQ 64
#define NK 64
#define NQT (T_/MQ)    // 32 q-tiles

struct AttnSmem {
    union {
        struct { float Qs[64][64]; float Ks[2][64][64]; } t;   // 48 KB
        struct { float cv[64][65]; int ci[64][65];
                 float ws[64][4];  int is[64][4]; } c;
    } u;
};

#define INS4(W0,W1,W2,W3,I0,I1,I2,I3,s,j)                                   \
    if ((s) > W3) { W3=(s); I3=(j);                                         \
        if (W3>W2){float tf_=W2;W2=W3;W3=tf_;int ti_=I2;I2=I3;I3=ti_;       \
            if (W2>W1){tf_=W1;W1=W2;W2=tf_;ti_=I1;I1=I2;I2=ti_;             \
                if (W1>W0){tf_=W0;W0=W1;W1=tf_;ti_=I0;I0=I1;I1=ti_;}}}}

__global__ __launch_bounds__(256)
void attn_kernel()
{
    __shared__ AttnSmem sm;
    int bh  = blockIdx.y;
    int tid = threadIdx.x;
    int qrow = tid >> 4;     // 0..15
    int kcol = tid & 15;     // 0..15

    const float* qb = g_q + (size_t)bh*HD_*T_;
    const float* kb = g_k + (size_t)bh*HD_*T_;
    const float* vb = g_v + (size_t)bh*T_*HD_;

    int lr = tid >> 2;            // 0..63 (= d)
    int lc = (tid & 3) * 16;      // 16 cols/thread

#pragma unroll 1
    for (int job = 0; job < 2; job++) {
        int qtile = job ? (NQT - 1 - blockIdx.x) : blockIdx.x;
        int q0 = qtile * MQ;

        // preload Q tile + K tile 0 (one cp.async group)
#pragma unroll
        for (int u = 0; u < 4; u++)
            cpa16(&sm.u.t.Qs[lr][lc + u*4], qb + (size_t)lr*T_ + q0 + lc + u*4);
#pragma unroll
        for (int u = 0; u < 4; u++)
            cpa16(&sm.u.t.Ks[0][lr][lc + u*4], kb + (size_t)lr*T_ + lc + u*4);
        cpa_commit();

        float w[4][4];
        int  id[4][4];
#pragma unroll
        for (int u = 0; u < 4; u++)
#pragma unroll
            for (int m = 0; m < 4; m++) { w[u][m] = -FLT_MAX; id[u][m] = 0; }

        const int ntiles = q0/NK + 1;
        for (int tile = 0; tile < ntiles; tile++) {
            cpa_wait<0>();
            __syncthreads();
            if (tile + 1 < ntiles) {
                int nb = (tile + 1) & 1;
                const float* src = kb + (size_t)lr*T_ + (tile+1)*NK + lc;
#pragma unroll
                for (int u = 0; u < 4; u++)
                    cpa16(&sm.u.t.Ks[nb][lr][lc + u*4], src + u*4);
                cpa_commit();
            }

            int cb = tile & 1;
            u64 acc2[4][2];    // 4 q-rows x 2 key-pairs
#pragma unroll
            for (int u = 0; u < 4; u++) { acc2[u][0] = 0ull; acc2[u][1] = 0ull; }

#pragma unroll 16
            for (int kk = 0; kk < 64; kk++) {
                float4 qv = *(const float4*)&sm.u.t.Qs[kk][qrow*4];
                ulonglong2 kp = *(const ulonglong2*)&sm.u.t.Ks[cb][kk][kcol*4];
                u64 a0 = splat2(qv.x), a1 = splat2(qv.y);
                u64 a2 = splat2(qv.z), a3 = splat2(qv.w);
                ffma2(acc2[0][0], a0, kp.x); ffma2(acc2[0][1], a0, kp.y);
                ffma2(acc2[1][0], a1, kp.x); ffma2(acc2[1][1], a1, kp.y);
                ffma2(acc2[2][0], a2, kp.x); ffma2(acc2[2][1], a2, kp.y);
                ffma2(acc2[3][0], a3, kp.x); ffma2(acc2[3][1], a3, kp.y);
            }

            int jb = tile*NK + kcol*4;
            if (tile == ntiles-1) {
#pragma unroll
                for (int u = 0; u < 4; u++) {
                    int qg = q0 + qrow*4 + u;
                    float2 p0 = unpack2(acc2[u][0]);
                    float2 p1 = unpack2(acc2[u][1]);
                    float sv[4] = {p0.x, p0.y, p1.x, p1.y};
#pragma unroll
                    for (int v = 0; v < 4; v++) {
                        float s = sv[v]; int j = jb + v;
                        if (j <= qg) { INS4(w[u][0],w[u][1],w[u][2],w[u][3],
                                            id[u][0],id[u][1],id[u][2],id[u][3], s, j); }
                    }
                }
            } else {
#pragma unroll
                for (int u = 0; u < 4; u++) {
                    float2 p0 = unpack2(acc2[u][0]);
                    float2 p1 = unpack2(acc2[u][1]);
                    float sv[4] = {p0.x, p0.y, p1.x, p1.y};
#pragma unroll
                    for (int v = 0; v < 4; v++) {
                        float s = sv[v]; int j = jb + v;
                        INS4(w[u][0],w[u][1],w[u][2],w[u][3],
                             id[u][0],id[u][1],id[u][2],id[u][3], s, j);
                    }
                }
            }
        }
        __syncthreads();   // last tile's reads done before candidate overlay

        // write per-thread candidates: cand[kcol*4+m][qrow*4+u] (scalar, transposed)
#pragma unroll
        for (int u = 0; u < 4; u++) {
            int q = qrow*4 + u;
#pragma unroll
            for (int m = 0; m < 4; m++) {
                int c = kcol*4 + m;
                sm.u.c.cv[c][q] = w[u][m];
                sm.u.c.ci[c][q] = id[u][m];
            }
        }
        __syncthreads();

        if (tid < 64) {
            int q = tid, qi = q0 + q;
            float m0=-FLT_MAX, m1=-FLT_MAX, m2=-FLT_MAX, m3=-FLT_MAX;
            int   j0_=0, j1_=0, j2_=0, j3_=0;
            for (int c = 0; c < 64; c++) {
                float s = sm.u.c.cv[c][q];
                int   j = sm.u.c.ci[c][q];
                INS4(m0,m1,m2,m3,j0_,j1_,j2_,j3_, s, j);
            }
            // kth = 4th largest of (causal scores U (T-1-i) masked zeros)
            int z  = T_ - 1 - qi;
            int nz = z < 4 ? z : 4;
            int p  = (m0 > 0.f) + (m1 > 0.f) + (m2 > 0.f) + (m3 > 0.f);
            float kth;
            if (p >= 4)            kth = m3;
            else if (p + nz >= 4)  kth = 0.f;
            else kth = (nz == 0) ? m3 : (nz == 1 ? m2 : (nz == 2 ? m1 : m0));

            sm.u.c.ws[q][0] = (m0 >= kth) ? tanhf(m0) : 0.f;  sm.u.c.is[q][0] = j0_;
            sm.u.c.ws[q][1] = (m1 >= kth) ? tanhf(m1) : 0.f;  sm.u.c.is[q][1] = j1_;
            sm.u.c.ws[q][2] = (m2 >= kth) ? tanhf(m2) : 0.f;  sm.u.c.is[q][2] = j2_;
            sm.u.c.ws[q][3] = (m3 >= kth) ? tanhf(m3) : 0.f;  sm.u.c.is[q][3] = j3_;
        }
        __syncthreads();

        // V gather + Y write: thread = (q, 16-dim group)
        {
            int q = tid >> 2, g = tid & 3;
            float4 a0 = make_float4(0,0,0,0), a1 = a0, a2 = a0, a3 = a0;
#pragma unroll
            for (int m = 0; m < 4; m++) {
                float wt = sm.u.c.ws[q][m];
                const float4* vp = (const float4*)(vb + (size_t)sm.u.c.is[q][m]*HD_ + g*16);
                float4 v0 = vp[0], v1 = vp[1], v2 = vp[2], v3 = vp[3];
                a0.x += wt*v0.x; a0.y += wt*v0.y; a0.z += wt*v0.z; a0.w += wt*v0.w;
                a1.x += wt*v1.x; a1.y += wt*v1.y; a1.z += wt*v1.z; a1.w += wt*v1.w;
                a2.x += wt*v2.x; a2.y += wt*v2.y; a2.z += wt*v2.z; a2.w += wt*v2.w;
                a3.x += wt*v3.x; a3.y += wt*v3.y; a3.z += wt*v3.z; a3.w += wt*v3.w;
            }
            int b = bh / H_, h = bh % H_;
            float4* yp = (float4*)(g_y + ((size_t)b*T_ + q0 + q)*C_ + h*HD_ + g*16);
            yp[0] = a0; yp[1] = a1; yp[2] = a2; yp[3] = a3;
        }
        __syncthreads();   // smem reused by next job's preload
    }
}

// ---------------------------------------------------------------------------
extern "C" void kernel_launch(void* const* d_in, const int* in_sizes, int n_in,
                              void* d_out, int out_size)
{
    const float* x  = (const float*)d_in[0];
    const float* Wq = (const float*)d_in[1];
    const float* Wk = (const float*)d_in[2];
    const float* Wv = (const float*)d_in[3];
    const float* Wp = (const float*)d_in[4];
    const float* qm = (const float*)d_in[5];
    float* out = (float*)d_out;

    gemm64<<<dim3(C_/GBN, (B_*T_)/GBM, 3), 256>>>(x, Wq, Wk, Wv, qm, nullptr, 0);
    attn_kernel<<<dim3(NQT/2, BH_), 256>>>();
    gemm64<<<dim3(C_/GBN, (B_*T_)/GBM, 1), 256>>>(nullptr, Wp, nullptr, nullptr, nullptr, out, 1);
}

// round 16
// speedup vs baseline: 1.0593x; 1.0593x over previous
#include <cuda_runtime.h>
#include <cfloat>

#define B_  2
#define T_  2048
#define C_  768
#define H_  12
#define HD_ 64
#define BH_ (B_*H_)

// ln(2048)/sqrt(64)
#define QSC 0.9530773732699245f

// scratch (static device globals; no allocs allowed)
__device__ float g_q[(size_t)BH_*HD_*T_];   // [bh][d][t], pre-scaled by QSC*qm[d]
__device__ float g_k[(size_t)BH_*HD_*T_];   // [bh][d][t]
__device__ float g_v[(size_t)BH_*T_*HD_];   // [bh][t][d]
__device__ float g_y[(size_t)B_*T_*C_];     // [b][t][h*HD]

// ---------------------------------------------------------------------------
// cp.async helpers
// ---------------------------------------------------------------------------
__device__ __forceinline__ void cpa16(void* dst, const void* src) {
    unsigned s = (unsigned)__cvta_generic_to_shared(dst);
    asm volatile("cp.async.cg.shared.global [%0], [%1], 16;\n" :: "r"(s), "l"(src));
}
__device__ __forceinline__ void cpa_commit() {
    asm volatile("cp.async.commit_group;\n");
}
template<int N> __device__ __forceinline__ void cpa_wait() {
    asm volatile("cp.async.wait_group %0;\n" :: "n"(N));
}

// ---------------------------------------------------------------------------
// packed f32x2 FMA helpers (SASS FFMA2 — halves issue pressure vs 2x FFMA)
// ---------------------------------------------------------------------------
typedef unsigned long long u64;

__device__ __forceinline__ void ffma2(u64& d, u64 a, u64 b) {
    asm("fma.rn.f32x2 %0, %1, %2, %0;" : "+l"(d) : "l"(a), "l"(b));
}
__device__ __forceinline__ u64 splat2(float x) {
    u64 r;
    asm("mov.b64 %0, {%1, %1};" : "=l"(r) : "f"(x));
    return r;
}
__device__ __forceinline__ float2 unpack2(u64 v) {
    float2 r;
    asm("mov.b64 {%0, %1}, %2;" : "=f"(r.x), "=f"(r.y) : "l"(v));
    return r;
}

// ---------------------------------------------------------------------------
// GEMM (round-14 config + 3-stage cp.async pipeline): C[4096,768] = A @ W,
// 64x128 tiles, BK=16, 256 threads, 4x8 micro-tile, FFMA2.
// Depth-3 buffers + wait_group<1>: one copy stays in flight during compute.
// mode: 0=q(transposed+scaled), 1=k(transposed), 2=v(row), 3=proj(out).
// ---------------------------------------------------------------------------
#define GBM 64
#define GBN 128
#define GBK 16

__global__ __launch_bounds__(256)
void gemm64(const float* __restrict__ Asrc,
            const float* __restrict__ W0, const float* __restrict__ W1,
            const float* __restrict__ W2, const float* __restrict__ qm,
            float* __restrict__ outp, int proj)
{
    __shared__ float As[3][GBM][GBK];   // 12 KB
    __shared__ float Bs[3][GBK][GBN];   // 24 KB

    int mode = proj ? 3 : blockIdx.z;
    const float* W = (mode == 1) ? W1 : (mode == 2 ? W2 : W0);
    const float* A = proj ? (const float*)g_y : Asrc;

    int tid  = threadIdx.x;
    int row0 = blockIdx.y * GBM;
    int col0 = blockIdx.x * GBN;

    int ar = tid >> 2, ac = (tid & 3) * 4;     // A tile: 64 x 16
    int br = tid >> 4, bc = (tid & 15) * 8;    // B tile: 16 x 128
    int ty = tid >> 4, tx = tid & 15;

    const int NIT = C_ / GBK;    // 48

    // preload k-slices 0 and 1 (two commit groups)
#pragma unroll
    for (int p = 0; p < 2; p++) {
        int k0 = p * GBK;
        cpa16(&As[p][ar][ac],   &A[(size_t)(row0 + ar)*C_ + k0 + ac]);
        cpa16(&Bs[p][br][bc],   &W[(size_t)(k0 + br)*C_ + col0 + bc]);
        cpa16(&Bs[p][br][bc+4], &W[(size_t)(k0 + br)*C_ + col0 + bc + 4]);
        cpa_commit();
    }

    u64 acc2[4][4];   // 4 rows x 4 col-pairs
#pragma unroll
    for (int i = 0; i < 4; i++)
#pragma unroll
        for (int j = 0; j < 4; j++) acc2[i][j] = 0ull;

    int cb = 0;       // buffer of current tile (it % 3, tracked incrementally)
    int pb = 2;       // buffer for tile it+2
    for (int it = 0; it < NIT; it++) {
        if (it + 1 < NIT) cpa_wait<1>(); else cpa_wait<0>();
        __syncthreads();
        if (it + 2 < NIT) {
            int k0 = (it + 2) * GBK;
            cpa16(&As[pb][ar][ac],   &A[(size_t)(row0 + ar)*C_ + k0 + ac]);
            cpa16(&Bs[pb][br][bc],   &W[(size_t)(k0 + br)*C_ + col0 + bc]);
            cpa16(&Bs[pb][br][bc+4], &W[(size_t)(k0 + br)*C_ + col0 + bc + 4]);
            cpa_commit();
        }

#pragma unroll
        for (int kb = 0; kb < 4; kb++) {
            float a_[4][4];
            *(float4*)a_[0] = *(const float4*)&As[cb][ty*4+0][kb*4];
            *(float4*)a_[1] = *(const float4*)&As[cb][ty*4+1][kb*4];
            *(float4*)a_[2] = *(const float4*)&As[cb][ty*4+2][kb*4];
            *(float4*)a_[3] = *(const float4*)&As[cb][ty*4+3][kb*4];
#pragma unroll
            for (int kl = 0; kl < 4; kl++) {
                ulonglong2 b01 = *(const ulonglong2*)&Bs[cb][kb*4+kl][tx*4];
                ulonglong2 b23 = *(const ulonglong2*)&Bs[cb][kb*4+kl][64 + tx*4];
#pragma unroll
                for (int i = 0; i < 4; i++) {
                    u64 ap = splat2(a_[i][kl]);
                    ffma2(acc2[i][0], ap, b01.x);
                    ffma2(acc2[i][1], ap, b01.y);
                    ffma2(acc2[i][2], ap, b23.x);
                    ffma2(acc2[i][3], ap, b23.y);
                }
            }
        }
        cb = (cb == 2) ? 0 : cb + 1;
        pb = (pb == 2) ? 0 : pb + 1;
    }

    // unpack accumulators: acc[i][j] covers cols col0 + {tx*4..+3, 64+tx*4..+3}
    float acc[4][8];
#pragma unroll
    for (int i = 0; i < 4; i++) {
#pragma unroll
        for (int p = 0; p < 4; p++) {
            float2 v = unpack2(acc2[i][p]);
            acc[i][p*2]   = v.x;
            acc[i][p*2+1] = v.y;
        }
    }

    int m0 = row0 + ty*4;
    if (mode == 3) {
#pragma unroll
        for (int i = 0; i < 4; i++) {
            float* dst = &outp[(size_t)(m0 + i)*C_ + col0 + tx*4];
            *(float4*)dst      = make_float4(acc[i][0],acc[i][1],acc[i][2],acc[i][3]);
            *(float4*)(dst+64) = make_float4(acc[i][4],acc[i][5],acc[i][6],acc[i][7]);
        }
    } else {
        int b  = m0 >> 11, t0 = m0 & (T_-1);
        int h0 = col0 >> 6;
        if (mode == 2) {
#pragma unroll
            for (int i = 0; i < 4; i++) {
                float* d0p = &g_v[((size_t)(b*H_ + h0  )*T_ + (t0+i))*HD_ + tx*4];
                float* d1p = &g_v[((size_t)(b*H_ + h0+1)*T_ + (t0+i))*HD_ + tx*4];
                *(float4*)d0p = make_float4(acc[i][0],acc[i][1],acc[i][2],acc[i][3]);
                *(float4*)d1p = make_float4(acc[i][4],acc[i][5],acc[i][6],acc[i][7]);
            }
        } else {
            float* dstb = (mode == 0) ? g_q : g_k;
            size_t base0 = (size_t)(b*H_ + h0  )*HD_*T_;
            size_t base1 = (size_t)(b*H_ + h0+1)*HD_*T_;
#pragma unroll
            for (int e = 0; e < 4; e++) {
                int d = tx*4 + e;
                float sc = (mode == 0) ? QSC * __ldg(&qm[d]) : 1.f;
                *(float4*)&dstb[base0 + (size_t)d*T_ + t0] =
                    make_float4(acc[0][e]*sc, acc[1][e]*sc, acc[2][e]*sc, acc[3][e]*sc);
                *(float4*)&dstb[base1 + (size_t)d*T_ + t0] =
                    make_float4(acc[0][4+e]*sc, acc[1][4+e]*sc,
                                acc[2][4+e]*sc, acc[3][4+e]*sc);
            }
        }
    }
}

// ---------------------------------------------------------------------------
// GEMM-tiled sparse top-4 causal attention (round-14 committed, verbatim):
// MQ=64, NK=64, 256 threads, FFMA2, pair-balanced grid (16, 24), single-
// barrier tile loop. CTA x runs q-tile x then q-tile 31-x (uniform 33 tiles).
// ---------------------------------------------------------------------------
#define MQ 64
#define NK 64
#define NQT (T_/MQ)    // 32 q-tiles

struct AttnSmem {
    union {
        struct { float Qs[64][64]; float Ks[2][64][64]; } t;   // 48 KB
        struct { float cv[64][65]; int ci[64][65];
                 float ws[64][4];  int is[64][4]; } c;
    } u;
};

#define INS4(W0,W1,W2,W3,I0,I1,I2,I3,s,j)                                   \
    if ((s) > W3) { W3=(s); I3=(j);                                         \
        if (W3>W2){float tf_=W2;W2=W3;W3=tf_;int ti_=I2;I2=I3;I3=ti_;       \
            if (W2>W1){tf_=W1;W1=W2;W2=tf_;ti_=I1;I1=I2;I2=ti_;             \
                if (W1>W0){tf_=W0;W0=W1;W1=tf_;ti_=I0;I0=I1;I1=ti_;}}}}

__global__ __launch_bounds__(256)
void attn_kernel()
{
    __shared__ AttnSmem sm;
    int bh  = blockIdx.y;
    int tid = threadIdx.x;
    int qrow = tid >> 4;     // 0..15
    int kcol = tid & 15;     // 0..15

    const float* qb = g_q + (size_t)bh*HD_*T_;
    const float* kb = g_k + (size_t)bh*HD_*T_;
    const float* vb = g_v + (size_t)bh*T_*HD_;

    int lr = tid >> 2;            // 0..63 (= d)
    int lc = (tid & 3) * 16;      // 16 cols/thread

#pragma unroll 1
    for (int job = 0; job < 2; job++) {
        int qtile = job ? (NQT - 1 - blockIdx.x) : blockIdx.x;
        int q0 = qtile * MQ;

        // preload Q tile + K tile 0 (one cp.async group)
#pragma unroll
        for (int u = 0; u < 4; u++)
            cpa16(&sm.u.t.Qs[lr][lc + u*4], qb + (size_t)lr*T_ + q0 + lc + u*4);
#pragma unroll
        for (int u = 0; u < 4; u++)
            cpa16(&sm.u.t.Ks[0][lr][lc + u*4], kb + (size_t)lr*T_ + lc + u*4);
        cpa_commit();

        float w[4][4];
        int  id[4][4];
#pragma unroll
        for (int u = 0; u < 4; u++)
#pragma unroll
            for (int m = 0; m < 4; m++) { w[u][m] = -FLT_MAX; id[u][m] = 0; }

        const int ntiles = q0/NK + 1;
        for (int tile = 0; tile < ntiles; tile++) {
            cpa_wait<0>();
            __syncthreads();
            if (tile + 1 < ntiles) {
                int nb = (tile + 1) & 1;
                const float* src = kb + (size_t)lr*T_ + (tile+1)*NK + lc;
#pragma unroll
                for (int u = 0; u < 4; u++)
                    cpa16(&sm.u.t.Ks[nb][lr][lc + u*4], src + u*4);
                cpa_commit();
            }

            int cb = tile & 1;
            u64 acc2[4][2];    // 4 q-rows x 2 key-pairs
#pragma unroll
            for (int u = 0; u < 4; u++) { acc2[u][0] = 0ull; acc2[u][1] = 0ull; }

#pragma unroll 16
            for (int kk = 0; kk < 64; kk++) {
                float4 qv = *(const float4*)&sm.u.t.Qs[kk][qrow*4];
                ulonglong2 kp = *(const ulonglong2*)&sm.u.t.Ks[cb][kk][kcol*4];
                u64 a0 = splat2(qv.x), a1 = splat2(qv.y);
                u64 a2 = splat2(qv.z), a3 = splat2(qv.w);
                ffma2(acc2[0][0], a0, kp.x); ffma2(acc2[0][1], a0, kp.y);
                ffma2(acc2[1][0], a1, kp.x); ffma2(acc2[1][1], a1, kp.y);
                ffma2(acc2[2][0], a2, kp.x); ffma2(acc2[2][1], a2, kp.y);
                ffma2(acc2[3][0], a3, kp.x); ffma2(acc2[3][1], a3, kp.y);
            }

            int jb = tile*NK + kcol*4;
            if (tile == ntiles-1) {
#pragma unroll
                for (int u = 0; u < 4; u++) {
                    int qg = q0 + qrow*4 + u;
                    float2 p0 = unpack2(acc2[u][0]);
                    float2 p1 = unpack2(acc2[u][1]);
                    float sv[4] = {p0.x, p0.y, p1.x, p1.y};
#pragma unroll
                    for (int v = 0; v < 4; v++) {
                        float s = sv[v]; int j = jb + v;
                        if (j <= qg) { INS4(w[u][0],w[u][1],w[u][2],w[u][3],
                                            id[u][0],id[u][1],id[u][2],id[u][3], s, j); }
                    }
                }
            } else {
#pragma unroll
                for (int u = 0; u < 4; u++) {
                    float2 p0 = unpack2(acc2[u][0]);
                    float2 p1 = unpack2(acc2[u][1]);
                    float sv[4] = {p0.x, p0.y, p1.x, p1.y};
#pragma unroll
                    for (int v = 0; v < 4; v++) {
                        float s = sv[v]; int j = jb + v;
                        INS4(w[u][0],w[u][1],w[u][2],w[u][3],
                             id[u][0],id[u][1],id[u][2],id[u][3], s, j);
                    }
                }
            }
        }
        __syncthreads();   // last tile's reads done before candidate overlay

        // write per-thread candidates: cand[kcol*4+m][qrow*4+u] (scalar, transposed)
#pragma unroll
        for (int u = 0; u < 4; u++) {
            int q = qrow*4 + u;
#pragma unroll
            for (int m = 0; m < 4; m++) {
                int c = kcol*4 + m;
                sm.u.c.cv[c][q] = w[u][m];
                sm.u.c.ci[c][q] = id[u][m];
            }
        }
        __syncthreads();

        if (tid < 64) {
            int q = tid, qi = q0 + q;
            float m0=-FLT_MAX, m1=-FLT_MAX, m2=-FLT_MAX, m3=-FLT_MAX;
            int   j0_=0, j1_=0, j2_=0, j3_=0;
            for (int c = 0; c < 64; c++) {
                float s = sm.u.c.cv[c][q];
                int   j = sm.u.c.ci[c][q];
                INS4(m0,m1,m2,m3,j0_,j1_,j2_,j3_, s, j);
            }
            // kth = 4th largest of (causal scores U (T-1-i) masked zeros)
            int z  = T_ - 1 - qi;
            int nz = z < 4 ? z : 4;
            int p  = (m0 > 0.f) + (m1 > 0.f) + (m2 > 0.f) + (m3 > 0.f);
            float kth;
            if (p >= 4)            kth = m3;
            else if (p + nz >= 4)  kth = 0.f;
            else kth = (nz == 0) ? m3 : (nz == 1 ? m2 : (nz == 2 ? m1 : m0));

            sm.u.c.ws[q][0] = (m0 >= kth) ? tanhf(m0) : 0.f;  sm.u.c.is[q][0] = j0_;
            sm.u.c.ws[q][1] = (m1 >= kth) ? tanhf(m1) : 0.f;  sm.u.c.is[q][1] = j1_;
            sm.u.c.ws[q][2] = (m2 >= kth) ? tanhf(m2) : 0.f;  sm.u.c.is[q][2] = j2_;
            sm.u.c.ws[q][3] = (m3 >= kth) ? tanhf(m3) : 0.f;  sm.u.c.is[q][3] = j3_;
        }
        __syncthreads();

        // V gather + Y write: thread = (q, 16-dim group)
        {
            int q = tid >> 2, g = tid & 3;
            float4 a0 = make_float4(0,0,0,0), a1 = a0, a2 = a0, a3 = a0;
#pragma unroll
            for (int m = 0; m < 4; m++) {
                float wt = sm.u.c.ws[q][m];
                const float4* vp = (const float4*)(vb + (size_t)sm.u.c.is[q][m]*HD_ + g*16);
                float4 v0 = vp[0], v1 = vp[1], v2 = vp[2], v3 = vp[3];
                a0.x += wt*v0.x; a0.y += wt*v0.y; a0.z += wt*v0.z; a0.w += wt*v0.w;
                a1.x += wt*v1.x; a1.y += wt*v1.y; a1.z += wt*v1.z; a1.w += wt*v1.w;
                a2.x += wt*v2.x; a2.y += wt*v2.y; a2.z += wt*v2.z; a2.w += wt*v2.w;
                a3.x += wt*v3.x; a3.y += wt*v3.y; a3.z += wt*v3.z; a3.w += wt*v3.w;
            }
            int b = bh / H_, h = bh % H_;
            float4* yp = (float4*)(g_y + ((size_t)b*T_ + q0 + q)*C_ + h*HD_ + g*16);
            yp[0] = a0; yp[1] = a1; yp[2] = a2; yp[3] = a3;
        }
        __syncthreads();   // smem reused by next job's preload
    }
}

// ---------------------------------------------------------------------------
extern "C" void kernel_launch(void* const* d_in, const int* in_sizes, int n_in,
                              void* d_out, int out_size)
{
    const float* x  = (const float*)d_in[0];
    const float* Wq = (const float*)d_in[1];
    const float* Wk = (const float*)d_in[2];
    const float* Wv = (const float*)d_in[3];
    const float* Wp = (const float*)d_in[4];
    const float* qm = (const float*)d_in[5];
    float* out = (float*)d_out;

    gemm64<<<dim3(C_/GBN, (B_*T_)/GBM, 3), 256>>>(x, Wq, Wk, Wv, qm, nullptr, 0);
    attn_kernel<<<dim3(NQT/2, BH_), 256>>>();
    gemm64<<<dim3(C_/GBN, (B_*T_)/GBM, 1), 256>>>(nullptr, Wp, nullptr, nullptr, nullptr, out, 1);
}